// round 11
// baseline (speedup 1.0000x reference)
#include <cuda_runtime.h>
#include <cstdint>

// Problem constants
#define B_   4
#define C_   128
#define H_   192
#define W_   192
#define HW_  (H_*W_)
#define K_   9
#define PAD  4
#define NOFF 81

// Tiling: 8 pixels/thread, occ 2, near-perfect wave quantization (576 blk / 296 = 1.95)
#define TH   8
#define TW   32
#define PXT  8
#define NTHREADS 288           // 4 wg * 9 io * 8 hr
#define CH   8
#define NSTAGE 16
#define YROWS 16               // TH + 2*PAD
#define YCHUNK 10              // stored y chunks/row: 40 floats, origin w0-4
#define YPITCH 44              // phase offsets {0,8,16,24}+{0,12} mod 32 all distinct
#define XPITCH 32
#define XSZ  (CH*TH*XPITCH)    // 2048 floats
#define YSZ  (CH*YROWS*YPITCH) // 5632 floats
#define BUFSZ (XSZ + YSZ)      // 7680 floats
#define SMEM_BYTES (2*BUFSZ*4) // 61440 bytes

typedef unsigned long long u64;

__device__ __forceinline__ u64 pack2(float lo, float hi) {
    u64 r;
    asm("mov.b64 %0, {%1, %2};" : "=l"(r) : "f"(lo), "f"(hi));
    return r;
}
__device__ __forceinline__ u64 ffma2u(u64 a, u64 b, u64 c) {
    u64 d;
    asm("fma.rn.f32x2 %0, %1, %2, %3;" : "=l"(d) : "l"(a), "l"(b), "l"(c));
    return d;
}
__device__ __forceinline__ float2 unpack2(u64 v) {
    float2 r;
    asm("mov.b64 {%0, %1}, %2;" : "=f"(r.x), "=f"(r.y) : "l"(v));
    return r;
}

__device__ __forceinline__ void cp16(uint32_t dst, const void* src, int srcsize) {
    asm volatile("cp.async.cg.shared.global [%0], [%1], 16, %2;"
                 :: "r"(dst), "l"(src), "r"(srcsize));
}
__device__ __forceinline__ void cp_commit() {
    asm volatile("cp.async.commit_group;");
}
template <int N>
__device__ __forceinline__ void cp_wait() {
    asm volatile("cp.async.wait_group %0;" :: "n"(N));
}

__global__ void __launch_bounds__(NTHREADS, 2)
corr_kernel(const float* __restrict__ x,
            const float* __restrict__ y,
            float* __restrict__ out) {
    extern __shared__ float sm[];

    const int tid = threadIdx.x;
    const int wg  = tid & 3;          // 4 pixel groups of 8
    const int io  = (tid >> 2) % 9;
    const int hr  = tid / 36;

    const int b  = blockIdx.z;
    const int h0 = blockIdx.y * TH;
    const int w0 = blockIdx.x * TW;

    const float* xb = x + (size_t)b * C_ * HW_;
    const float* yb = y + (size_t)b * C_ * HW_;

    const uint32_t sm_base = (uint32_t)__cvta_generic_to_shared(sm);

    // ---- stage prefetch: spread coalesced mapping, trimmed halo ----
    auto prefetch = [&](int s, int buf) {
        const int c0 = s * CH;
        const uint32_t xs_base = sm_base + (uint32_t)(buf * BUFSZ) * 4u;
        const uint32_t ys_base = xs_base + (uint32_t)XSZ * 4u;

        // x tile: CH*TH*8 = 512 float4, always in-bounds, 2 rounds
#pragma unroll
        for (int t = 0; t < 2; t++) {
            int idx = tid + t * NTHREADS;
            if (idx < CH * TH * 8) {
                int c  = idx >> 6;          // 64 float4 per channel
                int r  = (idx >> 3) & 7;
                int c4 = idx & 7;
                const float* src = xb + (size_t)(c0 + c) * HW_ + (h0 + r) * W_
                                   + w0 + c4 * 4;
                cp16(xs_base + (uint32_t)((c * TH + r) * XPITCH + c4 * 4) * 4u,
                     src, 16);
            }
        }
        // y halo tile: CH*16*10 = 1280 float4, origin (h0-4, w0-4), 5 rounds
#pragma unroll
        for (int k = 0; k < 5; k++) {
            int idx = tid + k * NTHREADS;
            if (idx < CH * YROWS * YCHUNK) {
                int c   = idx / (YROWS * YCHUNK);
                int rem = idx - c * (YROWS * YCHUNK);
                int r   = rem / YCHUNK;
                int q   = rem - r * YCHUNK;
                int gh  = h0 + r - PAD;
                int gw  = w0 - 4 + q * 4;
                bool ok = ((unsigned)gh < (unsigned)H_) &&
                          ((unsigned)gw <= (unsigned)(W_ - 4));
                const float* src = ok
                    ? yb + (size_t)(c0 + c) * HW_ + gh * W_ + gw
                    : yb;
                uint32_t dst = ys_base +
                    (uint32_t)(c * (YROWS * YPITCH) + r * YPITCH + q * 4) * 4u;
                cp16(dst, src, ok ? 16 : 0);
            }
        }
        cp_commit();
    };

    // accumulators: acc[j][q], pixel pair (2q, 2q+1), q in 0..3; 36 u64 = 72 regs
    u64 acc[K_][4];
#pragma unroll
    for (int j = 0; j < K_; j++)
#pragma unroll
        for (int q = 0; q < 4; q++) acc[j][q] = 0ull;

    prefetch(0, 0);

    for (int s = 0; s < NSTAGE; s++) {
        cp_wait<0>();              // stage-s group (issued a full stage ago) complete
        __syncthreads();           // publish stage s; buf (s+1)&1 free
        if (s + 1 < NSTAGE) prefetch(s + 1, (s + 1) & 1);   // overlaps compute(s)

        const int buf = s & 1;
        const float* xp   = sm + buf * BUFSZ + hr * XPITCH + wg * PXT;
        const float* yrow = sm + buf * BUFSZ + XSZ + (hr + io) * YPITCH + wg * PXT;

#pragma unroll
        for (int c = 0; c < CH; c++) {
            float4 xa = *(const float4*)(xp);
            float4 xcv = *(const float4*)(xp + 4);
            u64 xe0 = pack2(xa.x,  xa.y);    // coalescible packs
            u64 xe1 = pack2(xa.z,  xa.w);
            u64 xe2 = pack2(xcv.x, xcv.y);
            u64 xe3 = pack2(xcv.z, xcv.w);

            float4 y0 = *(const float4*)(yrow);
            float4 y1 = *(const float4*)(yrow + 4);
            float4 y2 = *(const float4*)(yrow + 8);
            float4 y3 = *(const float4*)(yrow + 12);
            float yv[16] = {y0.x, y0.y, y0.z, y0.w,
                            y1.x, y1.y, y1.z, y1.w,
                            y2.x, y2.y, y2.z, y2.w,
                            y3.x, y3.y, y3.z, y3.w};

            // even-aligned y pairs (coalescible packs)
            u64 ye[8];
#pragma unroll
            for (int t = 0; t < 8; t++) ye[t] = pack2(yv[2 * t], yv[2 * t + 1]);
            // odd-aligned y pairs (genuine movs, 7)
            u64 yo[7];
#pragma unroll
            for (int t = 0; t < 7; t++) yo[t] = pack2(yv[2 * t + 1], yv[2 * t + 2]);

            // even j = 2*je: pair q + je;  odd j = 2*jo+1: odd pair q + jo
#pragma unroll
            for (int je = 0; je < 5; je++) {
                acc[2 * je][0] = ffma2u(xe0, ye[je],     acc[2 * je][0]);
                acc[2 * je][1] = ffma2u(xe1, ye[je + 1], acc[2 * je][1]);
                acc[2 * je][2] = ffma2u(xe2, ye[je + 2], acc[2 * je][2]);
                acc[2 * je][3] = ffma2u(xe3, ye[je + 3], acc[2 * je][3]);
            }
#pragma unroll
            for (int jo = 0; jo < 4; jo++) {
                acc[2 * jo + 1][0] = ffma2u(xe0, yo[jo],     acc[2 * jo + 1][0]);
                acc[2 * jo + 1][1] = ffma2u(xe1, yo[jo + 1], acc[2 * jo + 1][1]);
                acc[2 * jo + 1][2] = ffma2u(xe2, yo[jo + 2], acc[2 * jo + 1][2]);
                acc[2 * jo + 1][3] = ffma2u(xe3, yo[jo + 3], acc[2 * jo + 1][3]);
            }

            xp   += TH * XPITCH;
            yrow += YROWS * YPITCH;
        }
    }

    // ---- epilogue: 9 offsets x 8 px = 2 float4 stores each ----
    const float inv_c = 1.0f / (float)C_;
    const int hrow = h0 + hr;
#pragma unroll
    for (int j = 0; j < K_; j++) {
        int o = io * K_ + j;
        float* op = out + (((size_t)b * NOFF + o) * H_ + hrow) * W_ + w0 + wg * PXT;
        float2 v0 = unpack2(acc[j][0]);
        float2 v1 = unpack2(acc[j][1]);
        float2 v2 = unpack2(acc[j][2]);
        float2 v3 = unpack2(acc[j][3]);
        *(float4*)op       = make_float4(v0.x * inv_c, v0.y * inv_c,
                                         v1.x * inv_c, v1.y * inv_c);
        *(float4*)(op + 4) = make_float4(v2.x * inv_c, v2.y * inv_c,
                                         v3.x * inv_c, v3.y * inv_c);
    }
}

extern "C" void kernel_launch(void* const* d_in, const int* in_sizes, int n_in,
                              void* d_out, int out_size) {
    const float* x = (const float*)d_in[0];
    const float* y = (const float*)d_in[1];
    float* out = (float*)d_out;

    static bool attr_set = false;
    if (!attr_set) {
        cudaFuncSetAttribute(corr_kernel,
                             cudaFuncAttributeMaxDynamicSharedMemorySize,
                             SMEM_BYTES);
        attr_set = true;
    }

    dim3 grid(W_ / TW, H_ / TH, B_);   // 6 x 24 x 4 = 576 blocks -> 1.95 waves @ occ 2
    corr_kernel<<<grid, NTHREADS, SMEM_BYTES>>>(x, y, out);
}

// round 12
// speedup vs baseline: 1.2600x; 1.2600x over previous
#include <cuda_runtime.h>
#include <cstdint>

// Problem constants
#define B_   4
#define C_   128
#define H_   192
#define W_   192
#define HW_  (H_*W_)
#define K_   9
#define PAD  4
#define NOFF 81

// Tiling (R10 operating point: PXT=4, occ 3)
#define TH   8
#define TW   16
#define PXT  4
#define NTHREADS 288           // 4 wg * 9 io * 8 hr
#define CH   8
#define NSTAGE 16
#define YROWS 16               // TH + 2*PAD
#define YCHUNK 6               // 24 stored y cols, origin w0-4
#define YPITCH 48              // odd-row-delta*48 ≡ 16 mod 32 -> conflict-free
#define XPITCH 16
#define XSZ  (CH*TH*XPITCH)    // 1024 floats
#define YSZ  (CH*YROWS*YPITCH) // 6144 floats
#define BUFSZ (XSZ + YSZ)      // 7168 floats
#define SMEM_BYTES (2*BUFSZ*4) // 57344 bytes

typedef unsigned long long u64;

__device__ __forceinline__ u64 pack2(float lo, float hi) {
    u64 r;
    asm("mov.b64 %0, {%1, %2};" : "=l"(r) : "f"(lo), "f"(hi));
    return r;
}
__device__ __forceinline__ u64 ffma2u(u64 a, u64 b, u64 c) {
    u64 d;
    asm("fma.rn.f32x2 %0, %1, %2, %3;" : "=l"(d) : "l"(a), "l"(b), "l"(c));
    return d;
}
__device__ __forceinline__ float2 unpack2(u64 v) {
    float2 r;
    asm("mov.b64 {%0, %1}, %2;" : "=f"(r.x), "=f"(r.y) : "l"(v));
    return r;
}

__device__ __forceinline__ void cp16(uint32_t dst, const void* src, int srcsize) {
    asm volatile("cp.async.cg.shared.global [%0], [%1], 16, %2;"
                 :: "r"(dst), "l"(src), "r"(srcsize));
}
__device__ __forceinline__ void cp_commit() {
    asm volatile("cp.async.commit_group;");
}
template <int N>
__device__ __forceinline__ void cp_wait() {
    asm volatile("cp.async.wait_group %0;" :: "n"(N));
}

__global__ void __launch_bounds__(NTHREADS, 3)
corr_kernel(const float* __restrict__ x,
            const float* __restrict__ y,
            float* __restrict__ out) {
    extern __shared__ float sm[];

    const int tid = threadIdx.x;
    const int wg  = tid & 3;
    const int io  = (tid >> 2) % 9;
    const int hr  = tid / 36;

    const int b  = blockIdx.z;
    const int h0 = blockIdx.y * TH;
    const int w0 = blockIdx.x * TW;

    const float* xb = x + (size_t)b * C_ * HW_;
    const float* yb = y + (size_t)b * C_ * HW_;

    const uint32_t sm_base = (uint32_t)__cvta_generic_to_shared(sm);

    // one y chunk: chunk id -> (c, r, q), single div-by-6 (mul-shift)
    auto y_chunk = [&](int c0, uint32_t ys_base, int chunk) {
        int t = chunk / 6;               // 0..127
        int q = chunk - 6 * t;
        int c = t >> 4;
        int r = t & 15;
        int gh = h0 + r - PAD;
        int gw = w0 - 4 + q * 4;
        bool ok = ((unsigned)gh < (unsigned)H_) &&
                  ((unsigned)gw <= (unsigned)(W_ - 4));
        const float* src = ok ? yb + (size_t)(c0 + c) * HW_ + gh * W_ + gw : yb;
        uint32_t dst = ys_base + (uint32_t)((c * YROWS + r) * YPITCH + q * 4) * 4u;
        cp16(dst, src, ok ? 16 : 0);
    };

    // part A: x tile (256 float4) + y chunks 0..255
    auto prefetchA = [&](int c0, int buf) {
        const uint32_t base = sm_base + (uint32_t)(buf * BUFSZ) * 4u;
        if (tid < 256) {
            int c  = tid >> 5;
            int r  = (tid >> 2) & 7;
            int c4 = tid & 3;
            const float* src = xb + (size_t)(c0 + c) * HW_ + (h0 + r) * W_ + w0 + c4 * 4;
            cp16(base + (uint32_t)((c * TH + r) * XPITCH + c4 * 4) * 4u, src, 16);
            y_chunk(c0, base + (uint32_t)XSZ * 4u, tid);
        }
        cp_commit();
    };
    // part B: y chunks 256..767
    auto prefetchB = [&](int c0, int buf) {
        const uint32_t base = sm_base + (uint32_t)(buf * BUFSZ) * 4u;
        if (tid < 256) {
            y_chunk(c0, base + (uint32_t)XSZ * 4u, tid + 256);
            y_chunk(c0, base + (uint32_t)XSZ * 4u, tid + 512);
        }
        cp_commit();
    };

    // accumulators: acc[j][q], pixel pair (2q, 2q+1); 18 u64 = 36 regs
    u64 acc[K_][2];
#pragma unroll
    for (int j = 0; j < K_; j++) { acc[j][0] = 0ull; acc[j][1] = 0ull; }

    // 4 channels of one stage
    auto compute_half = [&](int buf, int chlo) {
        const float* xp   = sm + buf * BUFSZ + chlo * (TH * XPITCH)
                            + hr * XPITCH + wg * PXT;
        const float* yrow = sm + buf * BUFSZ + XSZ + chlo * (YROWS * YPITCH)
                            + (hr + io) * YPITCH + wg * PXT;
#pragma unroll
        for (int c = 0; c < 4; c++) {
            float4 xa = *(const float4*)xp;
            u64 xe0 = pack2(xa.x, xa.y);
            u64 xe1 = pack2(xa.z, xa.w);

            float4 y0 = *(const float4*)(yrow);
            float4 y1 = *(const float4*)(yrow + 4);
            float4 y2 = *(const float4*)(yrow + 8);

            u64 ye[6];
            ye[0] = pack2(y0.x, y0.y); ye[1] = pack2(y0.z, y0.w);
            ye[2] = pack2(y1.x, y1.y); ye[3] = pack2(y1.z, y1.w);
            ye[4] = pack2(y2.x, y2.y); ye[5] = pack2(y2.z, y2.w);
            u64 yo[5];
            yo[0] = pack2(y0.y, y0.z); yo[1] = pack2(y0.w, y1.x);
            yo[2] = pack2(y1.y, y1.z); yo[3] = pack2(y1.w, y2.x);
            yo[4] = pack2(y2.y, y2.z);

#pragma unroll
            for (int je = 0; je < 5; je++) {
                acc[2 * je][0] = ffma2u(xe0, ye[je],     acc[2 * je][0]);
                acc[2 * je][1] = ffma2u(xe1, ye[je + 1], acc[2 * je][1]);
            }
#pragma unroll
            for (int jo = 0; jo < 4; jo++) {
                acc[2 * jo + 1][0] = ffma2u(xe0, yo[jo],     acc[2 * jo + 1][0]);
                acc[2 * jo + 1][1] = ffma2u(xe1, yo[jo + 1], acc[2 * jo + 1][1]);
            }

            xp   += TH * XPITCH;
            yrow += YROWS * YPITCH;
        }
    };

    prefetchA(0, 0);
    prefetchB(0, 0);

    // stages unrolled by 2: buf is compile-time constant
    for (int s = 0; s < NSTAGE; s += 2) {
        // ---- stage s (buf 0) ----
        cp_wait<0>();
        __syncthreads();
        prefetchA((s + 1) * CH, 1);     // head: x + first third of y
        compute_half(0, 0);
        prefetchB((s + 1) * CH, 1);     // mid: rest of y (smoother L1tex load)
        compute_half(0, 4);

        // ---- stage s+1 (buf 1) ----
        cp_wait<0>();
        __syncthreads();
        if (s + 2 < NSTAGE) prefetchA((s + 2) * CH, 0);
        compute_half(1, 0);
        if (s + 2 < NSTAGE) prefetchB((s + 2) * CH, 0);
        compute_half(1, 4);
    }

    // ---- epilogue: 9 float4 stores ----
    const float inv_c = 1.0f / (float)C_;
    const int hrow = h0 + hr;
#pragma unroll
    for (int j = 0; j < K_; j++) {
        int o = io * K_ + j;
        float* op = out + (((size_t)b * NOFF + o) * H_ + hrow) * W_ + w0 + wg * PXT;
        float2 v0 = unpack2(acc[j][0]);
        float2 v1 = unpack2(acc[j][1]);
        *(float4*)op = make_float4(v0.x * inv_c, v0.y * inv_c,
                                   v1.x * inv_c, v1.y * inv_c);
    }
}

extern "C" void kernel_launch(void* const* d_in, const int* in_sizes, int n_in,
                              void* d_out, int out_size) {
    const float* x = (const float*)d_in[0];
    const float* y = (const float*)d_in[1];
    float* out = (float*)d_out;

    static bool attr_set = false;
    if (!attr_set) {
        cudaFuncSetAttribute(corr_kernel,
                             cudaFuncAttributeMaxDynamicSharedMemorySize,
                             SMEM_BYTES);
        attr_set = true;
    }

    dim3 grid(W_ / TW, H_ / TH, B_);   // 12 x 24 x 4 = 1152 blocks
    corr_kernel<<<grid, NTHREADS, SMEM_BYTES>>>(x, y, out);
}